// round 2
// baseline (speedup 1.0000x reference)
#include <cuda_runtime.h>
#include <cuda_bf16.h>
#include <math_constants.h>

// Problem constants (shapes fixed by the dataset)
#define BATCH        32
#define HOPLEN       256
#define FRAMELEN     512
#define TMAXF        3749      // num_frames
#define CMAX         3750      // hop chunks per row
#define PADP         4096      // bitonic pad
#define SILF         18        // SILENCE_FRAMES
#define MINSP        6         // MIN_SPEECH_FRAMES
#define WNMAX        60        // ceil(3749/64)=59 (+pad)

// scratch: per-chunk sum of squares
__device__ float g_S[BATCH * CMAX];

// ---------------------------------------------------------------------------
// K1: sum-of-squares per 256-sample hop chunk. One warp per chunk.
// Reads 123 MB coalesced via float4; this is the HBM-bound kernel.
// ---------------------------------------------------------------------------
__global__ void chunk_sq_kernel(const float* __restrict__ W, int C, int n_samples, int total_chunks) {
    int warp = (blockIdx.x * blockDim.x + threadIdx.x) >> 5;
    int lane = threadIdx.x & 31;
    if (warp >= total_chunks) return;
    int b = warp / C;
    int j = warp - b * C;
    const float4* p = (const float4*)(W + (size_t)b * n_samples + (size_t)j * HOPLEN);
    float4 v0 = p[lane];
    float4 v1 = p[lane + 32];
    float s = v0.x*v0.x + v0.y*v0.y + v0.z*v0.z + v0.w*v0.w
            + v1.x*v1.x + v1.y*v1.y + v1.z*v1.z + v1.w*v1.w;
    #pragma unroll
    for (int o = 16; o; o >>= 1) s += __shfl_down_sync(0xFFFFFFFFu, s, o);
    if (lane == 0) g_S[warp] = s;
}

// any bit set in inclusive range [a,b] of packed mask M; span <= 19 bits
__device__ __forceinline__ bool any_bit(const unsigned long long* M, int a, int b) {
    int wa = a >> 6, wb = b >> 6;
    unsigned long long mb = (~0ULL) >> (63 - (b & 63));
    unsigned long long ma = (~0ULL) << (a & 63);
    if (wa == wb) return (M[wa] & ma & mb) != 0ULL;
    return ((M[wa] & ma) | (M[wb] & mb)) != 0ULL;
}

// ---------------------------------------------------------------------------
// K2: one block per batch row. energy -> sort -> quantile threshold ->
// mask bits -> run-group segmentation -> diff + prefix scan -> float out.
// ---------------------------------------------------------------------------
__global__ __launch_bounds__(1024, 1)
void vad_row_kernel(float* __restrict__ out, int T, int C) {
    int b   = blockIdx.x;
    int tid = threadIdx.x;

    __shared__ float e_s[TMAXF];
    __shared__ float sort_s[PADP];            // reused as int diff[] after threshold
    __shared__ unsigned long long mword[WNMAX];
    __shared__ unsigned long long lword[WNMAX];
    __shared__ float thr_sh;
    __shared__ int   nzero_sh;
    __shared__ int   warp_sums[32];

    if (tid == 0) nzero_sh = 0;
    if (tid < WNMAX) { mword[tid] = 0ULL; lword[tid] = 0ULL; }
    __syncthreads();

    // --- energy from chunk sums ---
    const float* Srow = g_S + (size_t)b * C;
    int local_neg = 0;
    for (int t = tid; t < T; t += 1024) {
        float e = (Srow[t] + Srow[t + 1]) * (1.0f / 512.0f);
        e_s[t] = e;
        if (e <= 0.0f) local_neg++;
    }
    #pragma unroll
    for (int o = 16; o; o >>= 1) local_neg += __shfl_down_sync(0xFFFFFFFFu, local_neg, o);
    if ((tid & 31) == 0 && local_neg) atomicAdd(&nzero_sh, local_neg);
    __syncthreads();

    // --- copy + pad for bitonic sort ---
    for (int i = tid; i < PADP; i += 1024) sort_s[i] = (i < T) ? e_s[i] : CUDART_INF_F;
    __syncthreads();

    // --- bitonic sort ascending ---
    for (int k = 2; k <= PADP; k <<= 1) {
        for (int j = k >> 1; j > 0; j >>= 1) {
            #pragma unroll
            for (int r = 0; r < PADP / 1024; r++) {
                int i = tid + r * 1024;
                int ixj = i ^ j;
                if (ixj > i) {
                    float a = sort_s[i], c = sort_s[ixj];
                    bool up = ((i & k) == 0);
                    if ((a > c) == up) { sort_s[i] = c; sort_s[ixj] = a; }
                }
            }
            __syncthreads();
        }
    }

    // --- quantile threshold (matches reference exactly) ---
    if (tid == 0) {
        int nzero = nzero_sh;
        int nz = T - nzero;
        float thr;
        if (nz > 0) {
            float pos  = 0.2f * (float)(nz - 1);
            float lo   = floorf(pos);
            float frac = pos - lo;
            int ilo = min(max(nzero + (int)lo, 0), T - 1);
            int ihi = min(max(nzero + (int)ceilf(pos), 0), T - 1);
            thr = sort_s[ilo] * (1.0f - frac) + sort_s[ihi] * frac;
        } else {
            thr = 0.01f;
        }
        thr_sh = thr;
    }
    __syncthreads();
    float thr = thr_sh;
    int wn = (T + 63) >> 6;

    // --- build packed mask words; then zero diff (aliases sort_s) ---
    int* diff = (int*)sort_s;  // size T+1 ints needed; PADP*4 bytes available
    for (int w = tid; w < wn; w += 1024) {
        unsigned long long bits = 0ULL;
        int base = w << 6;
        int lim = min(64, T - base);
        for (int k = 0; k < lim; k++)
            if (e_s[base + k] > thr) bits |= 1ULL << k;
        mword[w] = bits;
    }
    for (int i = tid; i <= T; i += 1024) diff[i] = 0;
    __syncthreads();

    // --- last flags: bit t is a group-last iff no 1 in (t, t+18] ---
    for (int w = tid; w < wn; w += 1024) {
        unsigned long long bits = mword[w];
        unsigned long long lb = 0ULL;
        int base = w << 6;
        while (bits) {
            int k = __ffsll((long long)bits) - 1;
            bits &= bits - 1ULL;
            int t = base + k;
            int a = t + 1, bnd = min(t + SILF, T - 1);
            bool any = (a <= bnd) ? any_bit(mword, a, bnd) : false;
            if (!any) lb |= 1ULL << k;
        }
        lword[w] = lb;
    }
    __syncthreads();

    // --- starts: bit t with no 1 in [t-18, t-1]; match to first last >= t ---
    for (int t = tid; t < T; t += 1024) {
        if (!((mword[t >> 6] >> (t & 63)) & 1ULL)) continue;
        int a = max(t - SILF, 0), bnd = t - 1;
        if (a <= bnd && any_bit(mword, a, bnd)) continue;  // not a group start
        // find matching group-last (guaranteed to exist within this group)
        int w = t >> 6;
        unsigned long long cur = lword[w] & ((~0ULL) << (t & 63));
        while (cur == 0ULL) { w++; cur = lword[w]; }
        int l = (w << 6) + __ffsll((long long)cur) - 1;
        bool closed = (l + SILF <= T - 1);
        int end = closed ? l : T;        // reference: closed end excludes the last 1
        if (end - t >= MINSP) { diff[t] = 1; diff[end] = -1; }
    }
    __syncthreads();

    // --- inclusive prefix scan over diff[0..T-1], out = (cum > 0) as float ---
    int idx0 = tid * 4;
    int v[4];
    int s = 0;
    #pragma unroll
    for (int q = 0; q < 4; q++) {
        int ii = idx0 + q;
        int d = (ii < T) ? diff[ii] : 0;
        s += d;
        v[q] = s;
    }
    int lane = tid & 31, wid = tid >> 5;
    int x = s;
    #pragma unroll
    for (int o = 1; o < 32; o <<= 1) {
        int y = __shfl_up_sync(0xFFFFFFFFu, x, o);
        if (lane >= o) x += y;
    }
    if (lane == 31) warp_sums[wid] = x;
    __syncthreads();
    if (wid == 0) {
        int ws = warp_sums[lane];
        int xx = ws;
        #pragma unroll
        for (int o = 1; o < 32; o <<= 1) {
            int y = __shfl_up_sync(0xFFFFFFFFu, xx, o);
            if (lane >= o) xx += y;
        }
        warp_sums[lane] = xx - ws;  // exclusive warp offsets
    }
    __syncthreads();
    int offset = warp_sums[wid] + (x - s);
    float* orow = out + (size_t)b * T;
    #pragma unroll
    for (int q = 0; q < 4; q++) {
        int ii = idx0 + q;
        if (ii < T) orow[ii] = ((offset + v[q]) > 0) ? 1.0f : 0.0f;
    }
}

extern "C" void kernel_launch(void* const* d_in, const int* in_sizes, int n_in,
                              void* d_out, int out_size) {
    const float* W = (const float*)d_in[0];
    int B = BATCH;
    int T = out_size / B;            // 3749
    int n_samples = in_sizes[0] / B; // 960000
    int C = T + 1;                   // 3750 hop chunks
    int total_chunks = B * C;

    int threads = 256;
    int blocks = (total_chunks * 32 + threads - 1) / threads;
    chunk_sq_kernel<<<blocks, threads>>>(W, C, n_samples, total_chunks);

    vad_row_kernel<<<B, 1024>>>((float*)d_out, T, C);
}

// round 3
// speedup vs baseline: 1.3147x; 1.3147x over previous
#include <cuda_runtime.h>
#include <cuda_bf16.h>
#include <math_constants.h>

#define BATCH        32
#define HOPLEN       256
#define TMAXF        3749      // num_frames
#define CMAX         3750      // hop chunks per row
#define SILF         18        // SILENCE_FRAMES
#define MINSP        6         // MIN_SPEECH_FRAMES
#define WN32         120       // ceil(3749/32)=118 (+pad)

// scratch: per-chunk sum of squares
__device__ float g_S[BATCH * CMAX];

// ---------------------------------------------------------------------------
// K1: sum-of-squares per 256-sample hop chunk. One warp per chunk.
// Reads 123 MB coalesced via 128-bit streaming loads; HBM-bound.
// ---------------------------------------------------------------------------
__global__ void chunk_sq_kernel(const float* __restrict__ W, int C, int n_samples, int total_chunks) {
    int warp = (blockIdx.x * blockDim.x + threadIdx.x) >> 5;
    int lane = threadIdx.x & 31;
    if (warp >= total_chunks) return;
    int b = warp / C;
    int j = warp - b * C;
    const float4* p = (const float4*)(W + (size_t)b * n_samples + (size_t)j * HOPLEN);
    float4 v0 = __ldcs(p + lane);
    float4 v1 = __ldcs(p + lane + 32);
    float s = v0.x*v0.x + v0.y*v0.y + v0.z*v0.z + v0.w*v0.w
            + v1.x*v1.x + v1.y*v1.y + v1.z*v1.z + v1.w*v1.w;
    #pragma unroll
    for (int o = 16; o; o >>= 1) s += __shfl_down_sync(0xFFFFFFFFu, s, o);
    if (lane == 0) g_S[warp] = s;
}

// any bit set in inclusive range [a,b] of packed 32-bit mask M; span <= 19 bits
__device__ __forceinline__ bool any_bit(const unsigned* M, int a, int b) {
    int wa = a >> 5, wb = b >> 5;
    unsigned ma = (~0u) << (a & 31);
    unsigned mb = (~0u) >> (31 - (b & 31));
    if (wa == wb) return (M[wa] & ma & mb) != 0u;
    return ((M[wa] & ma) | (M[wb] & mb)) != 0u;
}

// ---------------------------------------------------------------------------
// K2: one block per batch row. energy -> radix-select quantile threshold ->
// mask bits -> run-group segmentation -> diff + prefix scan -> float out.
// ---------------------------------------------------------------------------
__global__ __launch_bounds__(1024, 1)
void vad_row_kernel(float* __restrict__ out, int T, int C) {
    int b    = blockIdx.x;
    int tid  = threadIdx.x;
    int lane = tid & 31, wid = tid >> 5;

    __shared__ float    e_s[TMAXF];
    __shared__ int      diff[TMAXF + 2];
    __shared__ unsigned mword[WN32];
    __shared__ unsigned lword[WN32];
    __shared__ int      hist[256];
    __shared__ int      warp_sums[32];
    __shared__ int      nzero_sh, r_sh;
    __shared__ unsigned prefix_sh;
    __shared__ int      cle_sh;
    __shared__ unsigned mingt_sh;
    __shared__ float    thr_sh;

    if (tid == 0) { nzero_sh = 0; cle_sh = 0; mingt_sh = 0xFFFFFFFFu; }
    if (tid < WN32) { mword[tid] = 0u; lword[tid] = 0u; }
    __syncthreads();

    // --- energy from chunk sums; count non-positives ---
    const float* Srow = g_S + (size_t)b * C;
    int local_neg = 0;
    for (int t = tid; t < T; t += 1024) {
        float e = (Srow[t] + Srow[t + 1]) * (1.0f / 512.0f);
        e_s[t] = e;
        if (e <= 0.0f) local_neg++;
    }
    #pragma unroll
    for (int o = 16; o; o >>= 1) local_neg += __shfl_down_sync(0xFFFFFFFFu, local_neg, o);
    if (lane == 0 && local_neg) atomicAdd(&nzero_sh, local_neg);
    __syncthreads();

    // --- quantile rank setup (reference semantics) ---
    int nzero = nzero_sh;
    int nz = T - nzero;
    float pos  = 0.2f * (float)(nz - 1);
    float lo   = floorf(pos);
    float frac = pos - lo;
    int ilo = min(max(nzero + (int)lo, 0), T - 1);
    int ihi = min(max(nzero + (int)ceilf(pos), 0), T - 1);
    if (tid == 0) r_sh = ilo;

    // --- radix select: value at rank ilo (ascending). keys = float bits (all >= +0) ---
    unsigned prefix = 0, maskhi = 0;
    #pragma unroll
    for (int shift = 24; shift >= 0; shift -= 8) {
        if (tid < 256) hist[tid] = 0;
        __syncthreads();
        for (int i = tid; i < T; i += 1024) {
            unsigned k = __float_as_uint(e_s[i]);
            if ((k & maskhi) == prefix) atomicAdd(&hist[(k >> shift) & 255], 1);
        }
        __syncthreads();
        if (tid == 0) {
            int r = r_sh, c = 0, bin = 0;
            for (; bin < 255; bin++) {
                if (c + hist[bin] > r) break;
                c += hist[bin];
            }
            r_sh = r - c;
            prefix_sh = prefix | ((unsigned)bin << shift);
        }
        __syncthreads();
        prefix = prefix_sh;
        maskhi |= 0xFFu << shift;
    }
    float v_lo = __uint_as_float(prefix);

    // --- rank ihi value: count(<= v_lo) and min of keys > v_lo ---
    {
        int cle = 0;
        unsigned mingt = 0xFFFFFFFFu;
        for (int i = tid; i < T; i += 1024) {
            unsigned k = __float_as_uint(e_s[i]);
            if (k <= prefix) cle++;
            else mingt = min(mingt, k);
        }
        #pragma unroll
        for (int o = 16; o; o >>= 1) {
            cle  += __shfl_down_sync(0xFFFFFFFFu, cle, o);
            mingt = min(mingt, __shfl_down_sync(0xFFFFFFFFu, mingt, o));
        }
        if (lane == 0) {
            if (cle) atomicAdd(&cle_sh, cle);
            atomicMin(&mingt_sh, mingt);
        }
    }
    __syncthreads();
    if (tid == 0) {
        float v_hi = (cle_sh > ihi) ? v_lo : __uint_as_float(mingt_sh);
        float thr  = v_lo * (1.0f - frac) + v_hi * frac;
        thr_sh = (nz > 0) ? thr : 0.01f;
    }
    __syncthreads();
    float thr = thr_sh;

    // --- build packed mask words via ballot; zero diff ---
    #pragma unroll
    for (int r = 0; r < 4; r++) {
        int i = tid + r * 1024;
        bool pred = (i < T) && (e_s[i] > thr);
        unsigned w = __ballot_sync(0xFFFFFFFFu, pred);
        if (lane == 0 && (i >> 5) < WN32) mword[i >> 5] = w;
    }
    for (int i = tid; i <= T; i += 1024) diff[i] = 0;
    __syncthreads();

    // --- last flags: bit t is a group-last iff no 1 in (t, min(t+18, T-1)] ---
    for (int t = tid; t < T; t += 1024) {
        if (!((mword[t >> 5] >> (t & 31)) & 1u)) continue;
        int a = t + 1, bnd = min(t + SILF, T - 1);
        if (a <= bnd && any_bit(mword, a, bnd)) continue;
        atomicOr(&lword[t >> 5], 1u << (t & 31));
    }
    __syncthreads();

    // --- starts: bit t with no 1 in [t-18, t-1]; match to first last >= t ---
    for (int t = tid; t < T; t += 1024) {
        if (!((mword[t >> 5] >> (t & 31)) & 1u)) continue;
        int a = max(t - SILF, 0), bnd = t - 1;
        if (a <= bnd && any_bit(mword, a, bnd)) continue;   // not a group start
        int w = t >> 5;
        unsigned cur = lword[w] & ((~0u) << (t & 31));
        while (cur == 0u) { w++; cur = lword[w]; }
        int l = (w << 5) + __ffs(cur) - 1;
        bool closed = (l + SILF <= T - 1);
        int end = closed ? l : T;        // closed end excludes the last 1 (reference)
        if (end - t >= MINSP) { diff[t] = 1; diff[end] = -1; }
    }
    __syncthreads();

    // --- inclusive prefix scan over diff[0..T-1], out = (cum > 0) as float ---
    int idx0 = tid * 4;
    int v[4];
    int s = 0;
    #pragma unroll
    for (int q = 0; q < 4; q++) {
        int ii = idx0 + q;
        int d = (ii < T) ? diff[ii] : 0;
        s += d;
        v[q] = s;
    }
    int x = s;
    #pragma unroll
    for (int o = 1; o < 32; o <<= 1) {
        int y = __shfl_up_sync(0xFFFFFFFFu, x, o);
        if (lane >= o) x += y;
    }
    if (lane == 31) warp_sums[wid] = x;
    __syncthreads();
    if (wid == 0) {
        int ws = warp_sums[lane];
        int xx = ws;
        #pragma unroll
        for (int o = 1; o < 32; o <<= 1) {
            int y = __shfl_up_sync(0xFFFFFFFFu, xx, o);
            if (lane >= o) xx += y;
        }
        warp_sums[lane] = xx - ws;  // exclusive warp offsets
    }
    __syncthreads();
    int offset = warp_sums[wid] + (x - s);
    float* orow = out + (size_t)b * T;
    #pragma unroll
    for (int q = 0; q < 4; q++) {
        int ii = idx0 + q;
        if (ii < T) orow[ii] = ((offset + v[q]) > 0) ? 1.0f : 0.0f;
    }
}

extern "C" void kernel_launch(void* const* d_in, const int* in_sizes, int n_in,
                              void* d_out, int out_size) {
    const float* W = (const float*)d_in[0];
    int B = BATCH;
    int T = out_size / B;            // 3749
    int n_samples = in_sizes[0] / B; // 960000
    int C = T + 1;                   // 3750 hop chunks
    int total_chunks = B * C;

    int threads = 256;
    int blocks = (total_chunks * 32 + threads - 1) / threads;
    chunk_sq_kernel<<<blocks, threads>>>(W, C, n_samples, total_chunks);

    vad_row_kernel<<<B, 1024>>>((float*)d_out, T, C);
}

// round 4
// speedup vs baseline: 1.6567x; 1.2601x over previous
#include <cuda_runtime.h>
#include <cuda_bf16.h>
#include <math_constants.h>

#define BATCH        32
#define HOPLEN       256
#define TMAXF        3749      // num_frames
#define CMAX         3750      // hop chunks per row
#define SILF         18        // SILENCE_FRAMES
#define MINSP        6         // MIN_SPEECH_FRAMES
#define WN32         120       // ceil(3749/32)=118 (+pad)

// scratch: per-chunk sum of squares
__device__ float g_S[BATCH * CMAX];

// ---------------------------------------------------------------------------
// K1: sum-of-squares per 256-sample hop chunk. One warp per chunk.
// Reads 123 MB coalesced via 128-bit streaming loads; HBM-bound (~21 us).
// ---------------------------------------------------------------------------
__global__ void chunk_sq_kernel(const float* __restrict__ W, int C, int n_samples, int total_chunks) {
    int warp = (blockIdx.x * blockDim.x + threadIdx.x) >> 5;
    int lane = threadIdx.x & 31;
    if (warp >= total_chunks) return;
    int b = warp / C;
    int j = warp - b * C;
    const float4* p = (const float4*)(W + (size_t)b * n_samples + (size_t)j * HOPLEN);
    float4 v0 = __ldcs(p + lane);
    float4 v1 = __ldcs(p + lane + 32);
    float s = v0.x*v0.x + v0.y*v0.y + v0.z*v0.z + v0.w*v0.w
            + v1.x*v1.x + v1.y*v1.y + v1.z*v1.z + v1.w*v1.w;
    #pragma unroll
    for (int o = 16; o; o >>= 1) s += __shfl_down_sync(0xFFFFFFFFu, s, o);
    if (lane == 0) g_S[warp] = s;
}

// any bit set in inclusive range [a,b] of packed 32-bit mask M; span <= 19 bits
__device__ __forceinline__ bool any_bit(const unsigned* M, int a, int b) {
    int wa = a >> 5, wb = b >> 5;
    unsigned ma = (~0u) << (a & 31);
    unsigned mb = (~0u) >> (31 - (b & 31));
    if (wa == wb) return (M[wa] & ma & mb) != 0u;
    return ((M[wa] & ma) | (M[wb] & mb)) != 0u;
}

// ---------------------------------------------------------------------------
// K2: one block per batch row. energy -> radix-select quantile threshold ->
// mask bits -> run-group segmentation -> diff + prefix scan -> float out.
// ---------------------------------------------------------------------------
__global__ __launch_bounds__(1024, 1)
void vad_row_kernel(float* __restrict__ out, int T, int C) {
    int b    = blockIdx.x;
    int tid  = threadIdx.x;
    int lane = tid & 31, wid = tid >> 5;

    __shared__ float    e_s[TMAXF];
    __shared__ int      diff[TMAXF + 2];
    __shared__ unsigned mword[WN32];
    __shared__ unsigned lword[WN32];
    __shared__ int      hist[256];
    __shared__ int      warp_sums[32];
    __shared__ int      nzero_sh, r_sh;
    __shared__ unsigned prefix_sh;
    __shared__ int      cle_sh;
    __shared__ unsigned mingt_sh;
    __shared__ float    thr_sh;

    if (tid == 0) { nzero_sh = 0; cle_sh = 0; mingt_sh = 0xFFFFFFFFu; }
    __syncthreads();

    // --- energy from chunk sums; count non-positives ---
    const float* Srow = g_S + (size_t)b * C;
    int local_neg = 0;
    for (int t = tid; t < T; t += 1024) {
        float e = (Srow[t] + Srow[t + 1]) * (1.0f / 512.0f);
        e_s[t] = e;
        if (e <= 0.0f) local_neg++;
    }
    #pragma unroll
    for (int o = 16; o; o >>= 1) local_neg += __shfl_down_sync(0xFFFFFFFFu, local_neg, o);
    if (lane == 0 && local_neg) atomicAdd(&nzero_sh, local_neg);
    __syncthreads();

    // --- quantile rank setup (reference semantics) ---
    int nzero = nzero_sh;
    int nz = T - nzero;
    float pos  = 0.2f * (float)(nz - 1);
    float flo  = floorf(pos);
    float frac = pos - flo;
    int ilo = min(max(nzero + (int)flo, 0), T - 1);
    int ihi = min(max(nzero + (int)ceilf(pos), 0), T - 1);
    if (tid == 0) r_sh = ilo;
    __syncthreads();

    // --- radix select rank ilo: 4 x 8-bit passes, keys = float bits (all >= +0).
    //     Warp-aggregated histogram atomics + block-parallel bin selection. ---
    unsigned prefix = 0, maskhi = 0;
    #pragma unroll
    for (int shift = 24; shift >= 0; shift -= 8) {
        if (tid < 256) hist[tid] = 0;
        __syncthreads();
        #pragma unroll
        for (int base = 0; base < 4096; base += 1024) {
            int i = base + tid;
            bool ok = (i < T);
            unsigned k = ok ? __float_as_uint(e_s[i]) : 0u;
            ok = ok && ((k & maskhi) == prefix);
            int bin = ok ? (int)((k >> shift) & 255u) : -1;
            unsigned grp = __match_any_sync(0xFFFFFFFFu, bin);
            if (ok && lane == (__ffs(grp) - 1))
                atomicAdd(&hist[bin], __popc(grp));
        }
        __syncthreads();
        // block-parallel exclusive prefix over 256 bins (warps 0..7)
        int h = (tid < 256) ? hist[tid] : 0;
        int x = h;
        #pragma unroll
        for (int o = 1; o < 32; o <<= 1) {
            int y = __shfl_up_sync(0xFFFFFFFFu, x, o);
            if (lane >= o) x += y;
        }
        if (wid < 8 && lane == 31) warp_sums[wid] = x;
        __syncthreads();
        int rcur = r_sh;
        int off = 0;
        if (tid < 256) {
            #pragma unroll
            for (int w2 = 0; w2 < 8; w2++) off += (w2 < wid) ? warp_sums[w2] : 0;
        }
        int excl = x - h + off;
        __syncthreads();   // rcur reads complete before r_sh is overwritten
        if (tid < 256 && rcur >= excl && rcur < excl + h) {
            r_sh = rcur - excl;
            prefix_sh = prefix | ((unsigned)tid << shift);
        }
        __syncthreads();
        prefix = prefix_sh;
        maskhi |= 0xFFu << shift;
    }
    float v_lo = __uint_as_float(prefix);

    // --- rank ihi value: count(<= v_lo) and min of keys > v_lo ---
    {
        int cle = 0;
        unsigned mingt = 0xFFFFFFFFu;
        for (int i = tid; i < T; i += 1024) {
            unsigned k = __float_as_uint(e_s[i]);
            if (k <= prefix) cle++;
            else mingt = min(mingt, k);
        }
        #pragma unroll
        for (int o = 16; o; o >>= 1) {
            cle  += __shfl_down_sync(0xFFFFFFFFu, cle, o);
            mingt = min(mingt, __shfl_down_sync(0xFFFFFFFFu, mingt, o));
        }
        if (lane == 0) {
            if (cle) atomicAdd(&cle_sh, cle);
            atomicMin(&mingt_sh, mingt);
        }
    }
    __syncthreads();
    if (tid == 0) {
        float v_hi = (cle_sh > ihi) ? v_lo : __uint_as_float(mingt_sh);
        float thr  = v_lo * (1.0f - frac) + v_hi * frac;
        thr_sh = (nz > 0) ? thr : 0.01f;
    }
    __syncthreads();
    float thr = thr_sh;

    // --- build packed mask words via ballot; zero diff ---
    #pragma unroll
    for (int r = 0; r < 4; r++) {
        int i = tid + r * 1024;
        bool pred = (i < T) && (e_s[i] > thr);
        unsigned w = __ballot_sync(0xFFFFFFFFu, pred);
        if (lane == 0 && (i >> 5) < WN32) mword[i >> 5] = w;
    }
    for (int i = tid; i <= T; i += 1024) diff[i] = 0;
    __syncthreads();

    // --- last flags via ballot: bit t is group-last iff 1 at t and no 1 in (t, min(t+18,T-1)] ---
    #pragma unroll
    for (int r = 0; r < 4; r++) {
        int t = tid + r * 1024;
        bool pred = false;
        if (t < T && ((mword[t >> 5] >> (t & 31)) & 1u)) {
            int a = t + 1, bnd = min(t + SILF, T - 1);
            pred = !(a <= bnd && any_bit(mword, a, bnd));
        }
        unsigned w = __ballot_sync(0xFFFFFFFFu, pred);
        if (lane == 0 && (t >> 5) < WN32) lword[t >> 5] = w;
    }
    __syncthreads();

    // --- starts: bit t with no 1 in [t-18, t-1]; match to first last >= t ---
    for (int t = tid; t < T; t += 1024) {
        if (!((mword[t >> 5] >> (t & 31)) & 1u)) continue;
        int a = max(t - SILF, 0), bnd = t - 1;
        if (a <= bnd && any_bit(mword, a, bnd)) continue;   // not a group start
        int w = t >> 5;
        unsigned cur = lword[w] & ((~0u) << (t & 31));
        while (cur == 0u) { w++; cur = lword[w]; }
        int l = (w << 5) + __ffs(cur) - 1;
        bool closed = (l + SILF <= T - 1);
        int end = closed ? l : T;        // closed end excludes the last 1 (reference)
        if (end - t >= MINSP) { diff[t] = 1; diff[end] = -1; }
    }
    __syncthreads();

    // --- inclusive prefix scan over diff[0..T-1], out = (cum > 0) as float ---
    int idx0 = tid * 4;
    int v[4];
    int s = 0;
    #pragma unroll
    for (int q = 0; q < 4; q++) {
        int ii = idx0 + q;
        int d = (ii < T) ? diff[ii] : 0;
        s += d;
        v[q] = s;
    }
    int x2 = s;
    #pragma unroll
    for (int o = 1; o < 32; o <<= 1) {
        int y = __shfl_up_sync(0xFFFFFFFFu, x2, o);
        if (lane >= o) x2 += y;
    }
    if (lane == 31) warp_sums[wid] = x2;
    __syncthreads();
    if (wid == 0) {
        int ws = warp_sums[lane];
        int xx = ws;
        #pragma unroll
        for (int o = 1; o < 32; o <<= 1) {
            int y = __shfl_up_sync(0xFFFFFFFFu, xx, o);
            if (lane >= o) xx += y;
        }
        warp_sums[lane] = xx - ws;  // exclusive warp offsets
    }
    __syncthreads();
    int offset = warp_sums[wid] + (x2 - s);
    float* orow = out + (size_t)b * T;
    #pragma unroll
    for (int q = 0; q < 4; q++) {
        int ii = idx0 + q;
        if (ii < T) orow[ii] = ((offset + v[q]) > 0) ? 1.0f : 0.0f;
    }
}

extern "C" void kernel_launch(void* const* d_in, const int* in_sizes, int n_in,
                              void* d_out, int out_size) {
    const float* W = (const float*)d_in[0];
    int B = BATCH;
    int T = out_size / B;            // 3749
    int n_samples = in_sizes[0] / B; // 960000
    int C = T + 1;                   // 3750 hop chunks
    int total_chunks = B * C;

    int threads = 256;
    int blocks = (total_chunks * 32 + threads - 1) / threads;
    chunk_sq_kernel<<<blocks, threads>>>(W, C, n_samples, total_chunks);

    vad_row_kernel<<<B, 1024>>>((float*)d_out, T, C);
}

// round 5
// speedup vs baseline: 1.6867x; 1.0181x over previous
#include <cuda_runtime.h>
#include <cuda_bf16.h>

#define BATCH 32
#define T_    3749       // num frames
#define F4ROW 240000     // float4 per row (960000 floats)
#define EPB   32         // energies per K1 block
#define QPR   118        // ceil(3749/32) blocks per row
#define SILF  18
#define MINSP 6
#define WN32  120        // ceil(3749/32) mask words (+pad)
#define HB1   4096       // pass-1 bins (top 12 bits)

__device__ float g_E[BATCH * T_];
__device__ int   g_hist[BATCH * HB1];
__device__ int   g_nzero[BATCH];

// K0: zero scratch (histograms + nzero counters)
__global__ void zero_scratch_kernel() {
    int i = blockIdx.x * blockDim.x + threadIdx.x;
    if (i < BATCH * HB1) g_hist[i] = 0;
    if (i < BATCH) g_nzero[i] = 0;
}

// ---------------------------------------------------------------------------
// K1: each block reduces 32 chunks + 1 halo chunk of one row -> 32 energies,
// writes g_E, and builds the per-row top-12-bit histogram with warp-aggregated
// global atomics. HBM-bound; the extra work hides under memory latency.
// ---------------------------------------------------------------------------
__global__ __launch_bounds__(256) void energy_hist_kernel(const float* __restrict__ W, int n_samples) {
    int blk = blockIdx.x;
    int r = blk / QPR, q = blk - r * QPR;
    int tid = threadIdx.x, lane = tid & 31, wid = tid >> 5;
    __shared__ float s_part[66];
    __shared__ float s_chunk[33];

    const float4* base = (const float4*)(W + (size_t)r * n_samples) + q * 2048;
    int lim = min(2112, F4ROW - q * 2048);

    // 8 stripes of 256 float4; warp w in stripe s covers half of chunk s*4 + w/2
    #pragma unroll
    for (int s = 0; s < 8; s++) {
        int local = s * 256 + tid;
        float v = 0.f;
        if (local < lim) {
            float4 d = __ldcs(base + local);
            v = d.x*d.x + d.y*d.y + d.z*d.z + d.w*d.w;
        }
        #pragma unroll
        for (int o = 16; o; o >>= 1) v += __shfl_down_sync(0xFFFFFFFFu, v, o);
        if (lane == 0) s_part[s * 8 + wid] = v;
    }
    // halo chunk (index 32): 64 float4, warps 0-1
    {
        float v = 0.f;
        int local = 2048 + tid;
        if (tid < 64 && local < lim) {
            float4 d = __ldcs(base + local);
            v = d.x*d.x + d.y*d.y + d.z*d.z + d.w*d.w;
        }
        if (wid < 2) {
            #pragma unroll
            for (int o = 16; o; o >>= 1) v += __shfl_down_sync(0xFFFFFFFFu, v, o);
            if (lane == 0) s_part[64 + wid] = v;
        }
    }
    __syncthreads();
    if (tid < 33) {
        float sc;
        if (tid < 32) {
            int s0 = (tid >> 2) * 8 + (tid & 3) * 2;
            sc = s_part[s0] + s_part[s0 + 1];
        } else {
            sc = s_part[64] + s_part[65];
        }
        s_chunk[tid] = sc;
    }
    __syncthreads();
    if (tid < 32) {
        int ge = q * 32 + tid;
        bool valid = ge < T_;
        float e = 0.f;
        if (valid) {
            e = (s_chunk[tid] + s_chunk[tid + 1]) * (1.0f / 512.0f);
            g_E[r * T_ + ge] = e;
        }
        unsigned key = __float_as_uint(e);
        int bin = valid ? (int)(key >> 20) : -1;
        unsigned grp = __match_any_sync(0xFFFFFFFFu, bin);
        if (valid && lane == __ffs(grp) - 1)
            atomicAdd(&g_hist[r * HB1 + bin], __popc(grp));
        unsigned bz = __ballot_sync(0xFFFFFFFFu, valid && e <= 0.f);
        if (lane == 0 && bz) atomicAdd(&g_nzero[r], __popc(bz));
    }
}

__device__ __forceinline__ int warp_incl_scan(int x, int lane) {
    #pragma unroll
    for (int o = 1; o < 32; o <<= 1) {
        int y = __shfl_up_sync(0xFFFFFFFFu, x, o);
        if (lane >= o) x += y;
    }
    return x;
}
// exclusive block scan over 1024 threads; barrier-safe for repeated use
__device__ __forceinline__ int block_excl_scan(int v, int lane, int wid, int* warp_sums) {
    int x = warp_incl_scan(v, lane);
    if (lane == 31) warp_sums[wid] = x;
    __syncthreads();
    if (wid == 0) {
        int ws = warp_sums[lane];
        int xx = warp_incl_scan(ws, lane);
        warp_sums[lane] = xx - ws;
    }
    __syncthreads();
    int res = warp_sums[wid] + x - v;
    __syncthreads();
    return res;
}

// any bit set in inclusive range [a,b] of packed 32-bit mask M; span <= 19 bits
__device__ __forceinline__ bool any_bit(const unsigned* M, int a, int b) {
    int wa = a >> 5, wb = b >> 5;
    unsigned ma = (~0u) << (a & 31);
    unsigned mb = (~0u) >> (31 - (b & 31));
    if (wa == wb) return (M[wa] & ma & mb) != 0u;
    return ((M[wa] & ma) | (M[wb] & mb)) != 0u;
}

// ---------------------------------------------------------------------------
// K2: one block per row. pass-1 select from precomputed 4096-bin hist, then
// two 10-bit smem passes -> exact threshold -> mask -> segmentation -> out.
// ---------------------------------------------------------------------------
__global__ __launch_bounds__(1024, 1)
void vad_row_kernel(float* __restrict__ out) {
    int b = blockIdx.x, tid = threadIdx.x, lane = tid & 31, wid = tid >> 5;

    __shared__ float    e_s[T_];
    __shared__ int      diff[T_ + 2];
    __shared__ int      hist_s[1024];
    __shared__ unsigned mword[WN32], lword[WN32];
    __shared__ int      warp_sums[32];
    __shared__ int      r_sh;
    __shared__ unsigned prefix_sh;
    __shared__ int      cle_sh;
    __shared__ unsigned mingt_sh;
    __shared__ float    thr_sh;

    // load energies + init
    const float* Erow = g_E + b * T_;
    #pragma unroll
    for (int r = 0; r < 4; r++) { int i = r * 1024 + tid; if (i < T_) e_s[i] = Erow[i]; }
    for (int i = tid; i <= T_; i += 1024) diff[i] = 0;
    hist_s[tid] = 0;
    if (tid == 0) { cle_sh = 0; mingt_sh = 0xFFFFFFFFu; }

    int nzero = g_nzero[b];
    int nz = T_ - nzero;
    float pos  = 0.2f * (float)(nz - 1);
    float flo  = floorf(pos);
    float frac = pos - flo;
    int ilo = min(max(nzero + (int)flo, 0), T_ - 1);
    int ihi = min(max(nzero + (int)ceilf(pos), 0), T_ - 1);

    // --- pass 1: select top-12-bit bin from precomputed global hist ---
    int h4[4]; int base4 = tid << 2;
    #pragma unroll
    for (int j = 0; j < 4; j++) h4[j] = g_hist[b * HB1 + base4 + j];
    int tsum = h4[0] + h4[1] + h4[2] + h4[3];
    int texcl = block_excl_scan(tsum, lane, wid, warp_sums);
    {
        int cum = texcl;
        #pragma unroll
        for (int j = 0; j < 4; j++) {
            if (ilo >= cum && ilo < cum + h4[j]) { r_sh = ilo - cum; prefix_sh = (unsigned)(base4 + j) << 20; }
            cum += h4[j];
        }
    }
    __syncthreads();
    unsigned prefix = prefix_sh;

    // --- pass 2: bits 19..10 ---
    #pragma unroll
    for (int r = 0; r < 4; r++) {
        int i = r * 1024 + tid;
        bool ok = i < T_;
        unsigned k = ok ? __float_as_uint(e_s[i]) : 0u;
        ok = ok && ((k & 0xFFF00000u) == prefix);
        int bin = ok ? (int)((k >> 10) & 1023u) : -1;
        unsigned grp = __match_any_sync(0xFFFFFFFFu, bin);
        if (ok && lane == __ffs(grp) - 1) atomicAdd(&hist_s[bin], __popc(grp));
    }
    __syncthreads();
    {
        int h = hist_s[tid]; hist_s[tid] = 0;   // own-slot read+zero, no race
        int rr = r_sh;
        int excl = block_excl_scan(h, lane, wid, warp_sums);
        if (rr >= excl && rr < excl + h) { r_sh = rr - excl; prefix_sh = prefix | ((unsigned)tid << 10); }
    }
    __syncthreads();
    prefix = prefix_sh;

    // --- pass 3: bits 9..0 ---
    #pragma unroll
    for (int r = 0; r < 4; r++) {
        int i = r * 1024 + tid;
        bool ok = i < T_;
        unsigned k = ok ? __float_as_uint(e_s[i]) : 0u;
        ok = ok && ((k & 0xFFFFFC00u) == prefix);
        int bin = ok ? (int)(k & 1023u) : -1;
        unsigned grp = __match_any_sync(0xFFFFFFFFu, bin);
        if (ok && lane == __ffs(grp) - 1) atomicAdd(&hist_s[bin], __popc(grp));
    }
    __syncthreads();
    {
        int h = hist_s[tid];
        int rr = r_sh;
        int excl = block_excl_scan(h, lane, wid, warp_sums);
        if (rr >= excl && rr < excl + h) prefix_sh = prefix | (unsigned)tid;
    }
    __syncthreads();
    prefix = prefix_sh;
    float v_lo = __uint_as_float(prefix);

    // --- rank ihi value: count(<= v_lo) and min of keys > v_lo ---
    {
        int cle = 0;
        unsigned mingt = 0xFFFFFFFFu;
        for (int i = tid; i < T_; i += 1024) {
            unsigned k = __float_as_uint(e_s[i]);
            if (k <= prefix) cle++;
            else mingt = min(mingt, k);
        }
        #pragma unroll
        for (int o = 16; o; o >>= 1) {
            cle  += __shfl_down_sync(0xFFFFFFFFu, cle, o);
            mingt = min(mingt, __shfl_down_sync(0xFFFFFFFFu, mingt, o));
        }
        if (lane == 0) {
            if (cle) atomicAdd(&cle_sh, cle);
            atomicMin(&mingt_sh, mingt);
        }
    }
    __syncthreads();
    if (tid == 0) {
        float v_hi = (cle_sh > ihi) ? v_lo : __uint_as_float(mingt_sh);
        float thr  = v_lo * (1.0f - frac) + v_hi * frac;
        thr_sh = (nz > 0) ? thr : 0.01f;
    }
    __syncthreads();
    float thr = thr_sh;

    // --- packed mask words via ballot ---
    #pragma unroll
    for (int r = 0; r < 4; r++) {
        int i = r * 1024 + tid;
        bool pred = (i < T_) && (e_s[i] > thr);
        unsigned w = __ballot_sync(0xFFFFFFFFu, pred);
        if (lane == 0 && (i >> 5) < WN32) mword[i >> 5] = w;
    }
    __syncthreads();

    // --- last flags: bit t is group-last iff 1 at t and no 1 in (t, min(t+18,T-1)] ---
    #pragma unroll
    for (int r = 0; r < 4; r++) {
        int t = r * 1024 + tid;
        bool pred = false;
        if (t < T_ && ((mword[t >> 5] >> (t & 31)) & 1u)) {
            int a = t + 1, bnd = min(t + SILF, T_ - 1);
            pred = !(a <= bnd && any_bit(mword, a, bnd));
        }
        unsigned w = __ballot_sync(0xFFFFFFFFu, pred);
        if (lane == 0 && (t >> 5) < WN32) lword[t >> 5] = w;
    }
    __syncthreads();

    // --- starts: bit t with no 1 in [t-18, t-1]; match to first last >= t ---
    for (int t = tid; t < T_; t += 1024) {
        if (!((mword[t >> 5] >> (t & 31)) & 1u)) continue;
        int a = max(t - SILF, 0), bnd = t - 1;
        if (a <= bnd && any_bit(mword, a, bnd)) continue;   // not a group start
        int w = t >> 5;
        unsigned cur = lword[w] & ((~0u) << (t & 31));
        while (cur == 0u) { w++; cur = lword[w]; }
        int l = (w << 5) + __ffs(cur) - 1;
        bool closed = (l + SILF <= T_ - 1);
        int end = closed ? l : T_;       // closed end excludes the last 1 (reference)
        if (end - t >= MINSP) { diff[t] = 1; diff[end] = -1; }
    }
    __syncthreads();

    // --- inclusive prefix scan over diff[0..T-1], out = (cum > 0) as float ---
    int idx0 = tid * 4;
    int v[4];
    int s = 0;
    #pragma unroll
    for (int q = 0; q < 4; q++) {
        int ii = idx0 + q;
        int d = (ii < T_) ? diff[ii] : 0;
        s += d;
        v[q] = s;
    }
    int offset = block_excl_scan(s, lane, wid, warp_sums);
    float* orow = out + (size_t)b * T_;
    #pragma unroll
    for (int q = 0; q < 4; q++) {
        int ii = idx0 + q;
        if (ii < T_) orow[ii] = ((offset + v[q]) > 0) ? 1.0f : 0.0f;
    }
}

extern "C" void kernel_launch(void* const* d_in, const int* in_sizes, int n_in,
                              void* d_out, int out_size) {
    const float* W = (const float*)d_in[0];
    int n_samples = in_sizes[0] / BATCH;   // 960000

    zero_scratch_kernel<<<(BATCH * HB1 + 255) / 256, 256>>>();
    energy_hist_kernel<<<BATCH * QPR, 256>>>(W, n_samples);
    vad_row_kernel<<<BATCH, 1024>>>((float*)d_out);
}